// round 4
// baseline (speedup 1.0000x reference)
#include <cuda_runtime.h>
#include <math.h>
#include <float.h>

// ---------------- problem constants (fixed by dataset) ----------------
#define N_Q   65      // n = 1+W
#define M_KV  129     // m = 1+R
#define NH    8       // heads
#define HDIM  64      // head dim
#define CDIM  512     // model dim (= H*HD)
#define BQMAX 512     // B_ = 512

// ---------------- scratch (device globals; no allocation) -------------
__device__ float g_q  [(size_t)BQMAX * N_Q  * CDIM];        // (B_, n, H*HD)
__device__ float g_kv [(size_t)BQMAX * M_KV * 2 * CDIM];    // (B_, m, 2*H*HD)
__device__ float g_att[(size_t)BQMAX * N_Q  * CDIM];        // (B_, n, H*HD)

// =======================================================================
// Tiled FP32 GEMM:  C[M,N] = A[M,K] @ W[N,K]^T + bias[N]
// BM=128, BN=64, BK=16, 256 threads, per-thread 8x4.
// Requires M % 128 == 0, N % 64 == 0, K % 16 == 0 (true for all our calls).
// =======================================================================
__global__ __launch_bounds__(256) void gemm_bias_kernel(
    const float* __restrict__ A, const float* __restrict__ Wt,
    const float* __restrict__ bias, float* __restrict__ C,
    int K, int N)
{
    const int tid = threadIdx.x;
    const int tx = tid & 15;          // N direction (x4)
    const int ty = tid >> 4;          // M direction (x8)
    const int rowBase = blockIdx.y * 128;
    const int colBase = blockIdx.x * 64;

    __shared__ float As[16 * 132];    // [k][m], padded
    __shared__ float Bs[16 * 68];     // [k][n], padded

    float acc[8][4];
#pragma unroll
    for (int i = 0; i < 8; i++)
#pragma unroll
        for (int j = 0; j < 4; j++) acc[i][j] = 0.f;

    const float* Aptr = A  + (size_t)rowBase * K;
    const float* Wptr = Wt + (size_t)colBase * K;

    for (int k0 = 0; k0 < K; k0 += 16) {
        // ---- load A tile: 128 x 16 (512 float4, 2 per thread), transpose to smem
#pragma unroll
        for (int l = 0; l < 2; l++) {
            int f  = tid + l * 256;
            int r  = f >> 2;
            int c4 = f & 3;
            float4 v = *(const float4*)(Aptr + (size_t)r * K + k0 + c4 * 4);
            As[(c4 * 4 + 0) * 132 + r] = v.x;
            As[(c4 * 4 + 1) * 132 + r] = v.y;
            As[(c4 * 4 + 2) * 132 + r] = v.z;
            As[(c4 * 4 + 3) * 132 + r] = v.w;
        }
        // ---- load W tile: 64 x 16 (256 float4, 1 per thread), transpose
        {
            int r  = tid >> 2;
            int c4 = tid & 3;
            float4 v = *(const float4*)(Wptr + (size_t)r * K + k0 + c4 * 4);
            Bs[(c4 * 4 + 0) * 68 + r] = v.x;
            Bs[(c4 * 4 + 1) * 68 + r] = v.y;
            Bs[(c4 * 4 + 2) * 68 + r] = v.z;
            Bs[(c4 * 4 + 3) * 68 + r] = v.w;
        }
        __syncthreads();

#pragma unroll
        for (int k = 0; k < 16; k++) {
            float4 a0 = *(const float4*)&As[k * 132 + ty * 8];
            float4 a1 = *(const float4*)&As[k * 132 + ty * 8 + 4];
            float4 bb = *(const float4*)&Bs[k * 68  + tx * 4];
            float am[8] = {a0.x, a0.y, a0.z, a0.w, a1.x, a1.y, a1.z, a1.w};
            float bn[4] = {bb.x, bb.y, bb.z, bb.w};
#pragma unroll
            for (int i = 0; i < 8; i++)
#pragma unroll
                for (int j = 0; j < 4; j++)
                    acc[i][j] = fmaf(am[i], bn[j], acc[i][j]);
        }
        __syncthreads();
    }

    // ---- epilogue: add bias, store
    float4 bv = *(const float4*)&bias[colBase + tx * 4];
#pragma unroll
    for (int i = 0; i < 8; i++) {
        int row = rowBase + ty * 8 + i;
        float4 o;
        o.x = acc[i][0] + bv.x;
        o.y = acc[i][1] + bv.y;
        o.z = acc[i][2] + bv.z;
        o.w = acc[i][3] + bv.w;
        *(float4*)&C[(size_t)row * N + colBase + tx * 4] = o;
    }
}

// =======================================================================
// Fused window attention: one block per (batch-window b, head h)
//   S = (q k^T)*scale + bias ; mask ; softmax ; O = S v
// smem: qs[65][65] | kvs[129][65] (k then reused for v) | S[65][132]
// =======================================================================
#define QS_STRIDE 65
#define KS_STRIDE 65
#define S_STRIDE  132
#define SMEM_ATTN ((N_Q * QS_STRIDE + M_KV * KS_STRIDE + N_Q * S_STRIDE) * sizeof(float))

__global__ __launch_bounds__(256) void attn_kernel(
    const float* __restrict__ rel_table,   // (191, 8)
    const float* __restrict__ cls_self,    // (8)
    const float* __restrict__ cls_up,      // (8, 128)
    const float* __restrict__ cls_down,    // (8, 64)
    const int*   __restrict__ mask_left,   // (4, 65, 129)
    const int*   __restrict__ mask_right,  // (4, 65, 129)
    const int*   __restrict__ nW_ptr,
    float* __restrict__ out)               // g_att: (B_, n, H*HD)
{
    extern __shared__ float sm[];
    float* qs  = sm;                                  // 65 x 65
    float* kvs = qs  + N_Q * QS_STRIDE;               // 129 x 65
    float* S   = kvs + M_KV * KS_STRIDE;              // 65 x 132

    const int bid = blockIdx.x;
    const int b   = bid >> 3;
    const int h   = bid & 7;
    const int tid = threadIdx.x;
    const int tx  = tid & 15;
    const int ty  = tid >> 4;
    const int nW  = *nW_ptr;

    // ---- load q tile (65 x 64)
    for (int idx = tid; idx < N_Q * HDIM; idx += 256) {
        int i = idx >> 6, d = idx & 63;
        qs[i * QS_STRIDE + d] = g_q[((size_t)(b * N_Q + i)) * CDIM + h * HDIM + d];
    }
    // ---- load k tile (129 x 64)
    for (int idx = tid; idx < M_KV * HDIM; idx += 256) {
        int j = idx >> 6, d = idx & 63;
        kvs[j * KS_STRIDE + d] =
            g_kv[((size_t)(b * M_KV + j)) * (2 * CDIM) + h * HDIM + d];
    }
    __syncthreads();

    // ---- S = q k^T : per-thread 5x9 register tile (strided i = ti*16+ty)
    float acc[5][9];
#pragma unroll
    for (int ti = 0; ti < 5; ti++)
#pragma unroll
        for (int tj = 0; tj < 9; tj++) acc[ti][tj] = 0.f;

    for (int d = 0; d < HDIM; d++) {
        float a[5], bb[9];
#pragma unroll
        for (int ti = 0; ti < 5; ti++) {
            int i = ti * 16 + ty; if (i > 64) i = 64;
            a[ti] = qs[i * QS_STRIDE + d];
        }
#pragma unroll
        for (int tj = 0; tj < 9; tj++) {
            int j = tj * 16 + tx; if (j > 128) j = 128;
            bb[tj] = kvs[j * KS_STRIDE + d];
        }
#pragma unroll
        for (int ti = 0; ti < 5; ti++)
#pragma unroll
            for (int tj = 0; tj < 9; tj++)
                acc[ti][tj] = fmaf(a[ti], bb[tj], acc[ti][tj]);
    }

    // ---- bias + boundary-window mask + store S
    const int mc   = (nW < 4) ? nW : 4;
    const int w    = b % nW;
    const bool hasL = (w < mc);
    const bool hasR = (w >= nW - mc);
    const int* mlp = hasL ? mask_left  + (size_t)w * N_Q * M_KV : nullptr;
    const int* mrp = hasR ? mask_right + (size_t)(w - nW + 4) * N_Q * M_KV : nullptr;

#pragma unroll
    for (int ti = 0; ti < 5; ti++) {
        int i = ti * 16 + ty;
        if (i >= N_Q) continue;
#pragma unroll
        for (int tj = 0; tj < 9; tj++) {
            int j = tj * 16 + tx;
            if (j >= M_KV) continue;
            float s = acc[ti][tj] * 0.125f;   // HD^-0.5
            float bias;
            if (i == 0)      bias = (j == 0) ? cls_self[h] : cls_up[h * 128 + (j - 1)];
            else if (j == 0) bias = cls_down[h * 64 + (i - 1)];
            else             bias = rel_table[(i - j + 127) * NH + h];
            s += bias;
            bool msk = false;
            if (mlp && mlp[i * M_KV + j] == 1) msk = true;
            if (mrp && mrp[i * M_KV + j] == 1) msk = true;
            S[i * S_STRIDE + j] = msk ? -FLT_MAX : s;
        }
    }
    __syncthreads();

    // ---- reload v into the k buffer (k no longer needed)
    for (int idx = tid; idx < M_KV * HDIM; idx += 256) {
        int j = idx >> 6, d = idx & 63;
        kvs[j * KS_STRIDE + d] =
            g_kv[((size_t)(b * M_KV + j)) * (2 * CDIM) + CDIM + h * HDIM + d];
    }

    // ---- softmax: one warp per row (rows strided by 8)
    {
        const int warp = tid >> 5, lane = tid & 31;
        for (int r = warp; r < N_Q; r += 8) {
            float mx = -FLT_MAX;
            for (int c = lane; c < M_KV; c += 32) mx = fmaxf(mx, S[r * S_STRIDE + c]);
#pragma unroll
            for (int o = 16; o; o >>= 1) mx = fmaxf(mx, __shfl_xor_sync(0xffffffffu, mx, o));
            float sum = 0.f;
            for (int c = lane; c < M_KV; c += 32) {
                float e = expf(S[r * S_STRIDE + c] - mx);
                S[r * S_STRIDE + c] = e;
                sum += e;
            }
#pragma unroll
            for (int o = 16; o; o >>= 1) sum += __shfl_xor_sync(0xffffffffu, sum, o);
            float inv = 1.0f / sum;
            for (int c = lane; c < M_KV; c += 32) S[r * S_STRIDE + c] *= inv;
        }
    }
    __syncthreads();

    // ---- O = P @ v : per-thread 5x4 (i strided, d = td*16+tx)
    float o[5][4];
#pragma unroll
    for (int ti = 0; ti < 5; ti++)
#pragma unroll
        for (int td = 0; td < 4; td++) o[ti][td] = 0.f;

    for (int j = 0; j < M_KV; j++) {
        float p[5], vv[4];
#pragma unroll
        for (int ti = 0; ti < 5; ti++) {
            int i = ti * 16 + ty; if (i > 64) i = 64;
            p[ti] = S[i * S_STRIDE + j];
        }
#pragma unroll
        for (int td = 0; td < 4; td++)
            vv[td] = kvs[j * KS_STRIDE + td * 16 + tx];
#pragma unroll
        for (int ti = 0; ti < 5; ti++)
#pragma unroll
            for (int td = 0; td < 4; td++)
                o[ti][td] = fmaf(p[ti], vv[td], o[ti][td]);
    }

#pragma unroll
    for (int ti = 0; ti < 5; ti++) {
        int i = ti * 16 + ty;
        if (i >= N_Q) continue;
#pragma unroll
        for (int td = 0; td < 4; td++)
            out[((size_t)(b * N_Q + i)) * CDIM + h * HDIM + td * 16 + tx] = o[ti][td];
    }
}

// =======================================================================
// kernel_launch
// =======================================================================
extern "C" void kernel_launch(void* const* d_in, const int* in_sizes, int n_in,
                              void* d_out, int out_size)
{
    const float* x    = (const float*)d_in[0];   // (B_, 65, 512)
    const float* x_   = (const float*)d_in[1];   // (B_, 129, 512)
    const int*   mask_left  = (const int*)d_in[2];
    const int*   mask_right = (const int*)d_in[3];
    const int*   nW   = (const int*)d_in[4];
    const float* rel_table = (const float*)d_in[5];
    const float* cls_self  = (const float*)d_in[6];
    const float* cls_up    = (const float*)d_in[7];
    const float* cls_down  = (const float*)d_in[8];
    const float* Wq   = (const float*)d_in[9];
    const float* bq   = (const float*)d_in[10];
    const float* Wkv  = (const float*)d_in[11];
    const float* bkv  = (const float*)d_in[12];
    const float* Wp   = (const float*)d_in[13];
    const float* bp   = (const float*)d_in[14];
    float* out = (float*)d_out;

    const int Bq = in_sizes[0] / (N_Q * CDIM);   // 512

    float *qptr, *kvptr, *aptr;
    cudaGetSymbolAddress((void**)&qptr,  g_q);
    cudaGetSymbolAddress((void**)&kvptr, g_kv);
    cudaGetSymbolAddress((void**)&aptr,  g_att);

    static bool attr_set = false;
    cudaFuncSetAttribute(attn_kernel,
                         cudaFuncAttributeMaxDynamicSharedMemorySize,
                         (int)SMEM_ATTN);
    (void)attr_set;

    // 1) q = x @ Wq^T + bq         : M = B_*65, N = 512, K = 512
    {
        dim3 grid(CDIM / 64, (Bq * N_Q) / 128);
        gemm_bias_kernel<<<grid, 256>>>(x, Wq, bq, qptr, CDIM, CDIM);
    }
    // 2) kv = x_ @ Wkv^T + bkv     : M = B_*129, N = 1024, K = 512
    {
        dim3 grid((2 * CDIM) / 64, (Bq * M_KV) / 128);
        gemm_bias_kernel<<<grid, 256>>>(x_, Wkv, bkv, kvptr, CDIM, 2 * CDIM);
    }
    // 3) fused attention -> g_att
    {
        attn_kernel<<<Bq * NH, 256, SMEM_ATTN>>>(
            rel_table, cls_self, cls_up, cls_down,
            mask_left, mask_right, nW, aptr);
    }
    // 4) out = g_att @ Wp^T + bp   : M = B_*65, N = 512, K = 512
    {
        dim3 grid(CDIM / 64, (Bq * N_Q) / 128);
        gemm_bias_kernel<<<grid, 256>>>(aptr, Wp, bp, out, CDIM, CDIM);
    }
}

// round 5
// speedup vs baseline: 2.2160x; 2.2160x over previous
#include <cuda_runtime.h>
#include <math.h>
#include <float.h>
#include <stdint.h>

// ---------------- problem constants (fixed by dataset) ----------------
#define N_Q   65      // n = 1+W
#define M_KV  129     // m = 1+R
#define NH    8       // heads
#define HDIM  64      // head dim
#define CDIM  512     // model dim (= H*HD)
#define BQMAX 512     // B_ = 512

// ---------------- scratch (device globals; no allocation) -------------
__device__ float g_q  [(size_t)BQMAX * N_Q  * CDIM];        // (B_, n, H*HD)
__device__ float g_kv [(size_t)BQMAX * M_KV * 2 * CDIM];    // (B_, m, 2*H*HD)
__device__ float g_att[(size_t)BQMAX * N_Q  * CDIM];        // (B_, n, H*HD)

// =======================================================================
// TF32 tensor-core GEMM:  C[M,N] = A[M,K] @ W[N,K]^T + bias[N]
// BM=128, BN=128, BK=32, 256 threads (8 warps, 2x4), warp tile 64x32,
// mma.sync.aligned.m16n8k8.row.col.f32.tf32.tf32.f32
// Requires M%128==0, N%128==0, K%32==0 (true for all calls here).
// =======================================================================
#define GBM 128
#define GBN 128
#define GBK 32
#define AS_STRIDE 36
#define BS_STRIDE 36

__device__ __forceinline__ uint32_t f32_to_tf32(float f) {
    uint32_t u;
    asm("cvt.rna.tf32.f32 %0, %1;" : "=r"(u) : "f"(f));
    return u;
}

__device__ __forceinline__ void mma_tf32(float c[4], const uint32_t a[4],
                                         const uint32_t b[2]) {
    asm volatile(
        "mma.sync.aligned.m16n8k8.row.col.f32.tf32.tf32.f32 "
        "{%0,%1,%2,%3}, {%4,%5,%6,%7}, {%8,%9}, {%0,%1,%2,%3};"
        : "+f"(c[0]), "+f"(c[1]), "+f"(c[2]), "+f"(c[3])
        : "r"(a[0]), "r"(a[1]), "r"(a[2]), "r"(a[3]),
          "r"(b[0]), "r"(b[1]));
}

__global__ __launch_bounds__(256, 2) void gemm_tf32_kernel(
    const float* __restrict__ A, const float* __restrict__ W,
    const float* __restrict__ bias, float* __restrict__ C,
    int K, int N)
{
    __shared__ float As[GBM * AS_STRIDE];
    __shared__ float Bs[GBN * BS_STRIDE];

    const int tid    = threadIdx.x;
    const int warp   = tid >> 5;
    const int lane   = tid & 31;
    const int quad   = lane >> 2;      // 0..7
    const int tq     = lane & 3;       // 0..3
    const int warp_m = warp >> 2;      // 0..1  (64 rows each)
    const int warp_n = warp & 3;       // 0..3  (32 cols each)
    const int rowBase = blockIdx.y * GBM;
    const int colBase = blockIdx.x * GBN;

    float acc[4][4][4];
#pragma unroll
    for (int mt = 0; mt < 4; mt++)
#pragma unroll
        for (int nt = 0; nt < 4; nt++)
#pragma unroll
            for (int r = 0; r < 4; r++) acc[mt][nt][r] = 0.f;

    const float* Aptr = A + (size_t)rowBase * K;
    const float* Wptr = W + (size_t)colBase * K;

    for (int k0 = 0; k0 < K; k0 += GBK) {
        // ---- A tile: 128x32 f32 = 1024 float4, 4 per thread; round to tf32
#pragma unroll
        for (int i = 0; i < 4; i++) {
            int f  = tid + i * 256;
            int r  = f >> 3;
            int c4 = (f & 7) << 2;
            float4 v = *(const float4*)(Aptr + (size_t)r * K + k0 + c4);
            float4 t;
            t.x = __uint_as_float(f32_to_tf32(v.x));
            t.y = __uint_as_float(f32_to_tf32(v.y));
            t.z = __uint_as_float(f32_to_tf32(v.z));
            t.w = __uint_as_float(f32_to_tf32(v.w));
            *(float4*)&As[r * AS_STRIDE + c4] = t;
        }
        // ---- B tile: 128x32 (W rows are n-major, k contiguous)
#pragma unroll
        for (int i = 0; i < 4; i++) {
            int f  = tid + i * 256;
            int r  = f >> 3;
            int c4 = (f & 7) << 2;
            float4 v = *(const float4*)(Wptr + (size_t)r * K + k0 + c4);
            float4 t;
            t.x = __uint_as_float(f32_to_tf32(v.x));
            t.y = __uint_as_float(f32_to_tf32(v.y));
            t.z = __uint_as_float(f32_to_tf32(v.z));
            t.w = __uint_as_float(f32_to_tf32(v.w));
            *(float4*)&Bs[r * BS_STRIDE + c4] = t;
        }
        __syncthreads();

#pragma unroll
        for (int ks = 0; ks < 4; ks++) {
            const int kcol = ks * 8 + tq;
            uint32_t af[4][4];
            uint32_t bf[4][2];
#pragma unroll
            for (int mt = 0; mt < 4; mt++) {
                int r = warp_m * 64 + mt * 16 + quad;
                af[mt][0] = __float_as_uint(As[r * AS_STRIDE + kcol]);
                af[mt][1] = __float_as_uint(As[(r + 8) * AS_STRIDE + kcol]);
                af[mt][2] = __float_as_uint(As[r * AS_STRIDE + kcol + 4]);
                af[mt][3] = __float_as_uint(As[(r + 8) * AS_STRIDE + kcol + 4]);
            }
#pragma unroll
            for (int nt = 0; nt < 4; nt++) {
                int r = warp_n * 32 + nt * 8 + quad;
                bf[nt][0] = __float_as_uint(Bs[r * BS_STRIDE + kcol]);
                bf[nt][1] = __float_as_uint(Bs[r * BS_STRIDE + kcol + 4]);
            }
#pragma unroll
            for (int mt = 0; mt < 4; mt++)
#pragma unroll
                for (int nt = 0; nt < 4; nt++)
                    mma_tf32(acc[mt][nt], af[mt], bf[nt]);
        }
        __syncthreads();
    }

    // ---- epilogue: bias + store (c0,c1 and c2,c3 are n-contiguous pairs)
#pragma unroll
    for (int mt = 0; mt < 4; mt++) {
        int r0 = rowBase + warp_m * 64 + mt * 16 + quad;
#pragma unroll
        for (int nt = 0; nt < 4; nt++) {
            int c = colBase + warp_n * 32 + nt * 8 + 2 * tq;
            float2 bv = *(const float2*)&bias[c];
            float2 o0, o1;
            o0.x = acc[mt][nt][0] + bv.x;
            o0.y = acc[mt][nt][1] + bv.y;
            o1.x = acc[mt][nt][2] + bv.x;
            o1.y = acc[mt][nt][3] + bv.y;
            *(float2*)&C[(size_t)r0 * N + c]       = o0;
            *(float2*)&C[(size_t)(r0 + 8) * N + c] = o1;
        }
    }
}

// =======================================================================
// Fused window attention (unchanged from R4): one block per (b, h)
// =======================================================================
#define QS_STRIDE 65
#define KS_STRIDE 65
#define S_STRIDE  132
#define SMEM_ATTN ((N_Q * QS_STRIDE + M_KV * KS_STRIDE + N_Q * S_STRIDE) * sizeof(float))

__global__ __launch_bounds__(256) void attn_kernel(
    const float* __restrict__ rel_table,   // (191, 8)
    const float* __restrict__ cls_self,    // (8)
    const float* __restrict__ cls_up,      // (8, 128)
    const float* __restrict__ cls_down,    // (8, 64)
    const int*   __restrict__ mask_left,   // (4, 65, 129)
    const int*   __restrict__ mask_right,  // (4, 65, 129)
    const int*   __restrict__ nW_ptr,
    float* __restrict__ out)               // g_att: (B_, n, H*HD)
{
    extern __shared__ float sm[];
    float* qs  = sm;                                  // 65 x 65
    float* kvs = qs  + N_Q * QS_STRIDE;               // 129 x 65
    float* S   = kvs + M_KV * KS_STRIDE;              // 65 x 132

    const int bid = blockIdx.x;
    const int b   = bid >> 3;
    const int h   = bid & 7;
    const int tid = threadIdx.x;
    const int tx  = tid & 15;
    const int ty  = tid >> 4;
    const int nW  = *nW_ptr;

    for (int idx = tid; idx < N_Q * HDIM; idx += 256) {
        int i = idx >> 6, d = idx & 63;
        qs[i * QS_STRIDE + d] = g_q[((size_t)(b * N_Q + i)) * CDIM + h * HDIM + d];
    }
    for (int idx = tid; idx < M_KV * HDIM; idx += 256) {
        int j = idx >> 6, d = idx & 63;
        kvs[j * KS_STRIDE + d] =
            g_kv[((size_t)(b * M_KV + j)) * (2 * CDIM) + h * HDIM + d];
    }
    __syncthreads();

    float acc[5][9];
#pragma unroll
    for (int ti = 0; ti < 5; ti++)
#pragma unroll
        for (int tj = 0; tj < 9; tj++) acc[ti][tj] = 0.f;

    for (int d = 0; d < HDIM; d++) {
        float a[5], bb[9];
#pragma unroll
        for (int ti = 0; ti < 5; ti++) {
            int i = ti * 16 + ty; if (i > 64) i = 64;
            a[ti] = qs[i * QS_STRIDE + d];
        }
#pragma unroll
        for (int tj = 0; tj < 9; tj++) {
            int j = tj * 16 + tx; if (j > 128) j = 128;
            bb[tj] = kvs[j * KS_STRIDE + d];
        }
#pragma unroll
        for (int ti = 0; ti < 5; ti++)
#pragma unroll
            for (int tj = 0; tj < 9; tj++)
                acc[ti][tj] = fmaf(a[ti], bb[tj], acc[ti][tj]);
    }

    const int mc   = (nW < 4) ? nW : 4;
    const int w    = b % nW;
    const bool hasL = (w < mc);
    const bool hasR = (w >= nW - mc);
    const int* mlp = hasL ? mask_left  + (size_t)w * N_Q * M_KV : nullptr;
    const int* mrp = hasR ? mask_right + (size_t)(w - nW + 4) * N_Q * M_KV : nullptr;

#pragma unroll
    for (int ti = 0; ti < 5; ti++) {
        int i = ti * 16 + ty;
        if (i >= N_Q) continue;
#pragma unroll
        for (int tj = 0; tj < 9; tj++) {
            int j = tj * 16 + tx;
            if (j >= M_KV) continue;
            float s = acc[ti][tj] * 0.125f;
            float bias;
            if (i == 0)      bias = (j == 0) ? cls_self[h] : cls_up[h * 128 + (j - 1)];
            else if (j == 0) bias = cls_down[h * 64 + (i - 1)];
            else             bias = rel_table[(i - j + 127) * NH + h];
            s += bias;
            bool msk = false;
            if (mlp && mlp[i * M_KV + j] == 1) msk = true;
            if (mrp && mrp[i * M_KV + j] == 1) msk = true;
            S[i * S_STRIDE + j] = msk ? -FLT_MAX : s;
        }
    }
    __syncthreads();

    for (int idx = tid; idx < M_KV * HDIM; idx += 256) {
        int j = idx >> 6, d = idx & 63;
        kvs[j * KS_STRIDE + d] =
            g_kv[((size_t)(b * M_KV + j)) * (2 * CDIM) + CDIM + h * HDIM + d];
    }

    {
        const int warp = tid >> 5, lane = tid & 31;
        for (int r = warp; r < N_Q; r += 8) {
            float mx = -FLT_MAX;
            for (int c = lane; c < M_KV; c += 32) mx = fmaxf(mx, S[r * S_STRIDE + c]);
#pragma unroll
            for (int o = 16; o; o >>= 1) mx = fmaxf(mx, __shfl_xor_sync(0xffffffffu, mx, o));
            float sum = 0.f;
            for (int c = lane; c < M_KV; c += 32) {
                float e = expf(S[r * S_STRIDE + c] - mx);
                S[r * S_STRIDE + c] = e;
                sum += e;
            }
#pragma unroll
            for (int o = 16; o; o >>= 1) sum += __shfl_xor_sync(0xffffffffu, sum, o);
            float inv = 1.0f / sum;
            for (int c = lane; c < M_KV; c += 32) S[r * S_STRIDE + c] *= inv;
        }
    }
    __syncthreads();

    float o[5][4];
#pragma unroll
    for (int ti = 0; ti < 5; ti++)
#pragma unroll
        for (int td = 0; td < 4; td++) o[ti][td] = 0.f;

    for (int j = 0; j < M_KV; j++) {
        float p[5], vv[4];
#pragma unroll
        for (int ti = 0; ti < 5; ti++) {
            int i = ti * 16 + ty; if (i > 64) i = 64;
            p[ti] = S[i * S_STRIDE + j];
        }
#pragma unroll
        for (int td = 0; td < 4; td++)
            vv[td] = kvs[j * KS_STRIDE + td * 16 + tx];
#pragma unroll
        for (int ti = 0; ti < 5; ti++)
#pragma unroll
            for (int td = 0; td < 4; td++)
                o[ti][td] = fmaf(p[ti], vv[td], o[ti][td]);
    }

#pragma unroll
    for (int ti = 0; ti < 5; ti++) {
        int i = ti * 16 + ty;
        if (i >= N_Q) continue;
#pragma unroll
        for (int td = 0; td < 4; td++)
            out[((size_t)(b * N_Q + i)) * CDIM + h * HDIM + td * 16 + tx] = o[ti][td];
    }
}

// =======================================================================
// kernel_launch
// =======================================================================
extern "C" void kernel_launch(void* const* d_in, const int* in_sizes, int n_in,
                              void* d_out, int out_size)
{
    const float* x    = (const float*)d_in[0];   // (B_, 65, 512)
    const float* x_   = (const float*)d_in[1];   // (B_, 129, 512)
    const int*   mask_left  = (const int*)d_in[2];
    const int*   mask_right = (const int*)d_in[3];
    const int*   nW   = (const int*)d_in[4];
    const float* rel_table = (const float*)d_in[5];
    const float* cls_self  = (const float*)d_in[6];
    const float* cls_up    = (const float*)d_in[7];
    const float* cls_down  = (const float*)d_in[8];
    const float* Wq   = (const float*)d_in[9];
    const float* bq   = (const float*)d_in[10];
    const float* Wkv  = (const float*)d_in[11];
    const float* bkv  = (const float*)d_in[12];
    const float* Wp   = (const float*)d_in[13];
    const float* bp   = (const float*)d_in[14];
    float* out = (float*)d_out;

    const int Bq = in_sizes[0] / (N_Q * CDIM);   // 512

    float *qptr, *kvptr, *aptr;
    cudaGetSymbolAddress((void**)&qptr,  g_q);
    cudaGetSymbolAddress((void**)&kvptr, g_kv);
    cudaGetSymbolAddress((void**)&aptr,  g_att);

    cudaFuncSetAttribute(attn_kernel,
                         cudaFuncAttributeMaxDynamicSharedMemorySize,
                         (int)SMEM_ATTN);

    // 1) q = x @ Wq^T + bq : M = B_*65 (=33280), N = 512, K = 512
    {
        dim3 grid(CDIM / GBN, (Bq * N_Q) / GBM);
        gemm_tf32_kernel<<<grid, 256>>>(x, Wq, bq, qptr, CDIM, CDIM);
    }
    // 2) kv = x_ @ Wkv^T + bkv : M = B_*129 (=66048), N = 1024, K = 512
    {
        dim3 grid((2 * CDIM) / GBN, (Bq * M_KV) / GBM);
        gemm_tf32_kernel<<<grid, 256>>>(x_, Wkv, bkv, kvptr, CDIM, 2 * CDIM);
    }
    // 3) fused attention -> g_att
    {
        attn_kernel<<<Bq * NH, 256, SMEM_ATTN>>>(
            rel_table, cls_self, cls_up, cls_down,
            mask_left, mask_right, nW, aptr);
    }
    // 4) out = g_att @ Wp^T + bp : M = B_*65, N = 512, K = 512
    {
        dim3 grid(CDIM / GBN, (Bq * N_Q) / GBM);
        gemm_tf32_kernel<<<grid, 256>>>(aptr, Wp, bp, out, CDIM, CDIM);
    }
}

// round 6
// speedup vs baseline: 2.9300x; 1.3222x over previous
#include <cuda_runtime.h>
#include <math.h>
#include <float.h>
#include <stdint.h>

// ---------------- problem constants (fixed by dataset) ----------------
#define N_Q   65      // n = 1+W
#define M_KV  129     // m = 1+R
#define NH    8       // heads
#define HDIM  64      // head dim
#define CDIM  512     // model dim (= H*HD)
#define BQMAX 512     // B_ = 512

// ---------------- scratch (device globals; no allocation) -------------
__device__ float g_q  [(size_t)BQMAX * N_Q  * CDIM];        // (B_, n, H*HD)
__device__ float g_kv [(size_t)BQMAX * M_KV * 2 * CDIM];    // (B_, m, 2*H*HD)
__device__ float g_att[(size_t)BQMAX * N_Q  * CDIM];        // (B_, n, H*HD)

// ---------------- small helpers ----------------------------------------
__device__ __forceinline__ float tf32r(float f) {
    uint32_t u;
    asm("cvt.rna.tf32.f32 %0, %1;" : "=r"(u) : "f"(f));
    return __uint_as_float(u);
}
__device__ __forceinline__ uint32_t tf32u(float f) {
    uint32_t u;
    asm("cvt.rna.tf32.f32 %0, %1;" : "=r"(u) : "f"(f));
    return u;
}
__device__ __forceinline__ void mma_tf32(float c[4], const uint32_t a[4],
                                         const uint32_t b[2]) {
    asm volatile(
        "mma.sync.aligned.m16n8k8.row.col.f32.tf32.tf32.f32 "
        "{%0,%1,%2,%3}, {%4,%5,%6,%7}, {%8,%9}, {%0,%1,%2,%3};"
        : "+f"(c[0]), "+f"(c[1]), "+f"(c[2]), "+f"(c[3])
        : "r"(a[0]), "r"(a[1]), "r"(a[2]), "r"(a[3]),
          "r"(b[0]), "r"(b[1]));
}
__device__ __forceinline__ void cp16(float* smem, const float* g) {
    uint32_t a = (uint32_t)__cvta_generic_to_shared(smem);
    asm volatile("cp.async.cg.shared.global [%0], [%1], 16;\n"
                 :: "r"(a), "l"(g));
}

// =======================================================================
// TF32 tensor-core GEMM with cp.async 2-stage pipeline
//   C[M,N] = A[M,K] @ W[N,K]^T + bias[N]
// BM=128, BN=128, BK=32, 256 threads (8 warps, 2x4), warp tile 64x32.
// Raw fp32 staged in smem; cvt.rna->tf32 applied at fragment load.
// Requires M%128==0, N%128==0, K%32==0.
// =======================================================================
#define GBM 128
#define GBN 128
#define GBK 32
#define GST 36                 // smem row stride (words), 36%32=4 -> no conflicts
#define STAGE_WORDS (GBM * GST)
#define GEMM_SMEM_BYTES (4 * STAGE_WORDS * 4)   // 2 stages A + 2 stages B

__global__ __launch_bounds__(256, 2) void gemm_tf32_kernel(
    const float* __restrict__ A, const float* __restrict__ W,
    const float* __restrict__ bias, float* __restrict__ C,
    int K, int N)
{
    extern __shared__ float smg[];
    float* As = smg;                       // [2][128][36]
    float* Bs = smg + 2 * STAGE_WORDS;     // [2][128][36]

    const int tid    = threadIdx.x;
    const int warp   = tid >> 5;
    const int lane   = tid & 31;
    const int quad   = lane >> 2;
    const int tq     = lane & 3;
    const int warp_m = warp >> 2;          // 0..1
    const int warp_n = warp & 3;           // 0..3
    const int rowBase = blockIdx.y * GBM;
    const int colBase = blockIdx.x * GBN;

    const float* Aptr = A + (size_t)rowBase * K;
    const float* Wptr = W + (size_t)colBase * K;

    float acc[4][4][4];
#pragma unroll
    for (int mt = 0; mt < 4; mt++)
#pragma unroll
        for (int nt = 0; nt < 4; nt++)
#pragma unroll
            for (int r = 0; r < 4; r++) acc[mt][nt][r] = 0.f;

    const int NITER = K >> 5;

    // issue cp.async for pipeline stage of iteration `it`
    auto issue = [&](int it) {
        const int st = (it & 1) * STAGE_WORDS;
        const int k0 = it * GBK;
#pragma unroll
        for (int i = 0; i < 4; i++) {
            int f  = tid + i * 256;
            int rr = f >> 3;
            int c4 = (f & 7) << 2;
            cp16(As + st + rr * GST + c4, Aptr + (size_t)rr * K + k0 + c4);
            cp16(Bs + st + rr * GST + c4, Wptr + (size_t)rr * K + k0 + c4);
        }
    };

    issue(0);
    asm volatile("cp.async.commit_group;\n");

    for (int it = 0; it < NITER; it++) {
        if (it + 1 < NITER) {
            issue(it + 1);
            asm volatile("cp.async.commit_group;\n");
            asm volatile("cp.async.wait_group 1;\n");
        } else {
            asm volatile("cp.async.wait_group 0;\n");
        }
        __syncthreads();

        const float* as = As + (it & 1) * STAGE_WORDS;
        const float* bs = Bs + (it & 1) * STAGE_WORDS;

#pragma unroll
        for (int ks = 0; ks < 4; ks++) {
            const int kcol = ks * 8 + tq;
            uint32_t af[4][4];
            uint32_t bf[4][2];
#pragma unroll
            for (int mt = 0; mt < 4; mt++) {
                int r = warp_m * 64 + mt * 16 + quad;
                af[mt][0] = tf32u(as[r * GST + kcol]);
                af[mt][1] = tf32u(as[(r + 8) * GST + kcol]);
                af[mt][2] = tf32u(as[r * GST + kcol + 4]);
                af[mt][3] = tf32u(as[(r + 8) * GST + kcol + 4]);
            }
#pragma unroll
            for (int nt = 0; nt < 4; nt++) {
                int r = warp_n * 32 + nt * 8 + quad;
                bf[nt][0] = tf32u(bs[r * GST + kcol]);
                bf[nt][1] = tf32u(bs[r * GST + kcol + 4]);
            }
#pragma unroll
            for (int mt = 0; mt < 4; mt++)
#pragma unroll
                for (int nt = 0; nt < 4; nt++)
                    mma_tf32(acc[mt][nt], af[mt], bf[nt]);
        }
        __syncthreads();
    }

    // ---- epilogue: bias + store
#pragma unroll
    for (int mt = 0; mt < 4; mt++) {
        int r0 = rowBase + warp_m * 64 + mt * 16 + quad;
#pragma unroll
        for (int nt = 0; nt < 4; nt++) {
            int c = colBase + warp_n * 32 + nt * 8 + 2 * tq;
            float2 bv = *(const float2*)&bias[c];
            float2 o0, o1;
            o0.x = acc[mt][nt][0] + bv.x;
            o0.y = acc[mt][nt][1] + bv.y;
            o1.x = acc[mt][nt][2] + bv.x;
            o1.y = acc[mt][nt][3] + bv.y;
            *(float2*)&C[(size_t)r0 * N + c]       = o0;
            *(float2*)&C[(size_t)(r0 + 8) * N + c] = o1;
        }
    }
}

// =======================================================================
// Tensorized fused window attention: one block per (b, h), 256 threads.
// QK^T and PV on tf32 mma (rows 0..63), row 64 via scalar pass.
// smem layout (words):
//   [0 .. 9100)        : q (65 x QS) then S/P (65 x SS)   (overlaid)
//   [9100 .. 18892)    : k (144 x KS, rows>=129 zero) then v^T (64 x VS)
//   [18892 .. +384)    : bias tables (rel 191 | up 128 | down 64 | self 1)
// =======================================================================
#define QS 68      // q stride      (68 % 32 == 4  -> conflict-free frags)
#define KS 68      // k stride
#define SS 140     // S/P stride    (140 % 32 == 12 -> conflict-free frags)
#define VS 140     // v^T stride
#define OFF_KV  9100                        // 65*140
#define OFF_BR  (OFF_KV + 144 * KS)         // 9100 + 9792 = 18892
#define OFF_BU  (OFF_BR + 191)
#define OFF_BD  (OFF_BU + 128)
#define OFF_BSF (OFF_BD + 64)
#define ATTN_WORDS (OFF_BSF + 1)            // 19276
#define ATTN_SMEM_BYTES (ATTN_WORDS * 4)    // 77104

__global__ __launch_bounds__(256, 2) void attn_kernel(
    const float* __restrict__ rel_table,   // (191, 8)
    const float* __restrict__ cls_self,    // (8)
    const float* __restrict__ cls_up,      // (8, 128)
    const float* __restrict__ cls_down,    // (8, 64)
    const int*   __restrict__ mask_left,   // (4, 65, 129)
    const int*   __restrict__ mask_right,  // (4, 65, 129)
    const int*   __restrict__ nW_ptr,
    float* __restrict__ out)               // g_att: (B_, n, H*HD)
{
    extern __shared__ float sm[];
    float* Sq  = sm;               // q [i][d] (QS) -> later S/P [i][j] (SS)
    float* KV  = sm + OFF_KV;      // k [j][d] (KS) -> later v^T [d][j] (VS)
    float* brl = sm + OFF_BR;
    float* bup = sm + OFF_BU;
    float* bdn = sm + OFF_BD;
    float* bsf = sm + OFF_BSF;

    const int bid  = blockIdx.x;
    const int b    = bid >> 3;
    const int h    = bid & 7;
    const int tid  = threadIdx.x;
    const int warp = tid >> 5;
    const int lane = tid & 31;
    const int quad = lane >> 2;
    const int tq   = lane & 3;
    const int wm   = warp >> 1;    // 0..3 : rows 16*wm .. 16*wm+15
    const int wn   = warp & 1;     // 0..1 : j-halves / d-halves
    const int nW   = *nW_ptr;

    // ---- bias tables
    if (tid < 191) brl[tid] = rel_table[tid * NH + h];
    if (tid < 128) bup[tid] = cls_up[h * 128 + tid];
    if (tid < 64)  bdn[tid] = cls_down[h * 64 + tid];
    if (tid == 224) bsf[0]  = cls_self[h];

    // ---- load q (65 x 64), tf32-rounded
    for (int idx = tid; idx < N_Q * 16; idx += 256) {
        int i = idx >> 4, c4 = (idx & 15) << 2;
        float4 v = *(const float4*)&g_q[((size_t)(b * N_Q + i)) * CDIM + h * HDIM + c4];
        float4 t = { tf32r(v.x), tf32r(v.y), tf32r(v.z), tf32r(v.w) };
        *(float4*)&Sq[i * QS + c4] = t;
    }
    // ---- load k (129 x 64) tf32-rounded; zero pad rows 129..143
    for (int idx = tid; idx < 144 * 16; idx += 256) {
        int j = idx >> 4, c4 = (idx & 15) << 2;
        float4 t = {0.f, 0.f, 0.f, 0.f};
        if (j < M_KV) {
            float4 v = *(const float4*)&g_kv[((size_t)(b * M_KV + j)) * (2 * CDIM)
                                             + h * HDIM + c4];
            t.x = tf32r(v.x); t.y = tf32r(v.y); t.z = tf32r(v.z); t.w = tf32r(v.w);
        }
        *(float4*)&KV[j * KS + c4] = t;
    }
    __syncthreads();

    // ---- QK^T mma: rows 0..63; each warp 16 rows x 9 n-tiles (72 j-cols)
    const int nbase = wn * 72;
    float acc[9][4];
#pragma unroll
    for (int nt = 0; nt < 9; nt++)
#pragma unroll
        for (int r = 0; r < 4; r++) acc[nt][r] = 0.f;

#pragma unroll
    for (int ks = 0; ks < 8; ks++) {
        const int kc = ks * 8 + tq;
        const int row = wm * 16 + quad;
        uint32_t a[4];
        a[0] = __float_as_uint(Sq[row * QS + kc]);
        a[1] = __float_as_uint(Sq[(row + 8) * QS + kc]);
        a[2] = __float_as_uint(Sq[row * QS + kc + 4]);
        a[3] = __float_as_uint(Sq[(row + 8) * QS + kc + 4]);
#pragma unroll
        for (int nt = 0; nt < 9; nt++) {
            int jr = nbase + nt * 8 + quad;
            uint32_t bfr[2];
            bfr[0] = __float_as_uint(KV[jr * KS + kc]);
            bfr[1] = __float_as_uint(KV[jr * KS + kc + 4]);
            mma_tf32(acc[nt], a, bfr);
        }
    }

    // ---- row 64 scalar logits (q row 64 . k_j)
    float s64 = 0.f;
    if (tid < M_KV) {
#pragma unroll 8
        for (int d = 0; d < HDIM; d++)
            s64 += Sq[64 * QS + d] * KV[tid * KS + d];
    }
    __syncthreads();   // q & k fully consumed

    // ---- masks
    const int mc   = (nW < 4) ? nW : 4;
    const int w    = b % nW;
    const bool hasL = (w < mc);
    const bool hasR = (w >= nW - mc);
    const int* mlp = mask_left  + (size_t)w * N_Q * M_KV;
    const int* mrp = mask_right + (size_t)(w - nW + 4) * N_Q * M_KV;

    // ---- write S = scale*acc + bias, masked (rows 0..63)
#pragma unroll
    for (int nt = 0; nt < 9; nt++) {
        int j0 = nbase + nt * 8 + 2 * tq;
        int i0 = wm * 16 + quad;
#pragma unroll
        for (int e = 0; e < 4; e++) {
            int i = i0 + (e >> 1) * 8;
            int j = j0 + (e & 1);
            if (j >= M_KV) continue;
            float bias;
            if (i == 0)      bias = (j == 0) ? bsf[0] : bup[j - 1];
            else if (j == 0) bias = bdn[i - 1];
            else             bias = brl[i - j + 127];
            float s = acc[nt][e] * 0.125f + bias;
            if (hasL && mlp[i * M_KV + j] == 1) s = -FLT_MAX;
            if (hasR && mrp[i * M_KV + j] == 1) s = -FLT_MAX;
            Sq[i * SS + j] = s;
        }
    }
    // ---- row 64
    if (tid < M_KV) {
        int j = tid;
        float bias = (j == 0) ? bdn[63] : brl[64 - j + 127];
        float s = s64 * 0.125f + bias;
        if (hasL && mlp[64 * M_KV + j] == 1) s = -FLT_MAX;
        if (hasR && mrp[64 * M_KV + j] == 1) s = -FLT_MAX;
        Sq[64 * SS + j] = s;
    }
    // ---- zero S pad cols 129..139 (rows 0..64)
    for (int idx = tid; idx < N_Q * 11; idx += 256) {
        int i = idx / 11, c = M_KV + idx % 11;
        Sq[i * SS + c] = 0.f;
    }
    // ---- load v transposed (v^T [d][j]), tf32-rounded, zero j>=129
    for (int idx = tid; idx < 136 * HDIM; idx += 256) {
        int j = idx >> 6, d = idx & 63;
        float v = 0.f;
        if (j < M_KV)
            v = tf32r(g_kv[((size_t)(b * M_KV + j)) * (2 * CDIM) + CDIM + h * HDIM + d]);
        KV[d * VS + j] = v;
    }
    __syncthreads();

    // ---- softmax rows 0..64 (cols 0..128); write back tf32-rounded P
    for (int r = warp; r < N_Q; r += 8) {
        float mx = -FLT_MAX;
        for (int c = lane; c < M_KV; c += 32) mx = fmaxf(mx, Sq[r * SS + c]);
#pragma unroll
        for (int o = 16; o; o >>= 1) mx = fmaxf(mx, __shfl_xor_sync(0xffffffffu, mx, o));
        float sum = 0.f;
        float ev[5];
#pragma unroll
        for (int t = 0; t < 5; t++) {
            int c = lane + t * 32;
            float e = (c < M_KV) ? expf(Sq[r * SS + c] - mx) : 0.f;
            ev[t] = e;
            sum += e;
        }
#pragma unroll
        for (int o = 16; o; o >>= 1) sum += __shfl_xor_sync(0xffffffffu, sum, o);
        float inv = 1.0f / sum;
#pragma unroll
        for (int t = 0; t < 5; t++) {
            int c = lane + t * 32;
            if (c < M_KV) Sq[r * SS + c] = tf32r(ev[t] * inv);
        }
    }
    __syncthreads();

    // ---- PV mma: O[i][d] = sum_j P[i][j] * v[j][d];  K = 136 (17 ksteps)
    float acc2[4][4];
#pragma unroll
    for (int nt = 0; nt < 4; nt++)
#pragma unroll
        for (int r = 0; r < 4; r++) acc2[nt][r] = 0.f;

#pragma unroll
    for (int ks = 0; ks < 17; ks++) {
        const int kc = ks * 8 + tq;
        const int row = wm * 16 + quad;
        uint32_t a[4];
        a[0] = __float_as_uint(Sq[row * SS + kc]);
        a[1] = __float_as_uint(Sq[(row + 8) * SS + kc]);
        a[2] = __float_as_uint(Sq[row * SS + kc + 4]);
        a[3] = __float_as_uint(Sq[(row + 8) * SS + kc + 4]);
#pragma unroll
        for (int nt = 0; nt < 4; nt++) {
            int dr = wn * 32 + nt * 8 + quad;
            uint32_t bfr[2];
            bfr[0] = __float_as_uint(KV[dr * VS + kc]);
            bfr[1] = __float_as_uint(KV[dr * VS + kc + 4]);
            mma_tf32(acc2[nt], a, bfr);
        }
    }

    // ---- row 64 scalar PV
    float o64 = 0.f;
    if (tid < HDIM) {
        for (int j = 0; j < M_KV; j++)
            o64 += Sq[64 * SS + j] * KV[tid * VS + j];
    }

    // ---- write output rows 0..63
#pragma unroll
    for (int nt = 0; nt < 4; nt++) {
        int i0 = wm * 16 + quad;
        int d0 = wn * 32 + nt * 8 + 2 * tq;
        float2 o0 = { acc2[nt][0], acc2[nt][1] };
        float2 o1 = { acc2[nt][2], acc2[nt][3] };
        *(float2*)&out[((size_t)(b * N_Q + i0)) * CDIM + h * HDIM + d0]     = o0;
        *(float2*)&out[((size_t)(b * N_Q + i0 + 8)) * CDIM + h * HDIM + d0] = o1;
    }
    // ---- write row 64
    if (tid < HDIM)
        out[((size_t)(b * N_Q + 64)) * CDIM + h * HDIM + tid] = o64;
}

// =======================================================================
// kernel_launch
// =======================================================================
extern "C" void kernel_launch(void* const* d_in, const int* in_sizes, int n_in,
                              void* d_out, int out_size)
{
    const float* x    = (const float*)d_in[0];   // (B_, 65, 512)
    const float* x_   = (const float*)d_in[1];   // (B_, 129, 512)
    const int*   mask_left  = (const int*)d_in[2];
    const int*   mask_right = (const int*)d_in[3];
    const int*   nW   = (const int*)d_in[4];
    const float* rel_table = (const float*)d_in[5];
    const float* cls_self  = (const float*)d_in[6];
    const float* cls_up    = (const float*)d_in[7];
    const float* cls_down  = (const float*)d_in[8];
    const float* Wq   = (const float*)d_in[9];
    const float* bq   = (const float*)d_in[10];
    const float* Wkv  = (const float*)d_in[11];
    const float* bkv  = (const float*)d_in[12];
    const float* Wp   = (const float*)d_in[13];
    const float* bp   = (const float*)d_in[14];
    float* out = (float*)d_out;

    const int Bq = in_sizes[0] / (N_Q * CDIM);   // 512

    float *qptr, *kvptr, *aptr;
    cudaGetSymbolAddress((void**)&qptr,  g_q);
    cudaGetSymbolAddress((void**)&kvptr, g_kv);
    cudaGetSymbolAddress((void**)&aptr,  g_att);

    cudaFuncSetAttribute(gemm_tf32_kernel,
                         cudaFuncAttributeMaxDynamicSharedMemorySize,
                         GEMM_SMEM_BYTES);
    cudaFuncSetAttribute(attn_kernel,
                         cudaFuncAttributeMaxDynamicSharedMemorySize,
                         ATTN_SMEM_BYTES);

    // 1) q = x @ Wq^T + bq : M = B_*65 (=33280), N = 512, K = 512
    {
        dim3 grid(CDIM / GBN, (Bq * N_Q) / GBM);
        gemm_tf32_kernel<<<grid, 256, GEMM_SMEM_BYTES>>>(x, Wq, bq, qptr, CDIM, CDIM);
    }
    // 2) kv = x_ @ Wkv^T + bkv : M = B_*129 (=66048), N = 1024, K = 512
    {
        dim3 grid((2 * CDIM) / GBN, (Bq * M_KV) / GBM);
        gemm_tf32_kernel<<<grid, 256, GEMM_SMEM_BYTES>>>(x_, Wkv, bkv, kvptr, CDIM, 2 * CDIM);
    }
    // 3) fused tensorized attention -> g_att
    {
        attn_kernel<<<Bq * NH, 256, ATTN_SMEM_BYTES>>>(
            rel_table, cls_self, cls_up, cls_down,
            mask_left, mask_right, nW, aptr);
    }
    // 4) out = g_att @ Wp^T + bp : M = B_*65, N = 512, K = 512
    {
        dim3 grid(CDIM / GBN, (Bq * N_Q) / GBM);
        gemm_tf32_kernel<<<grid, 256, GEMM_SMEM_BYTES>>>(aptr, Wp, bp, out, CDIM, CDIM);
    }
}